// round 15
// baseline (speedup 1.0000x reference)
#include <cuda_runtime.h>
#include <cuda_bf16.h>
#include <math.h>

// dims: B=8, T_TEXT=256, T_MEL=1024, VOCAB=256, MEL=80, H=512, NH=8, HD=64

// ------------------------- scratch arena -----------------------------------
constexpr size_t OFF_X     = 0;                               // [2048,512]
constexpr size_t OFF_XGF   = OFF_X     + (size_t)2048*512;    // [2048,2048]
constexpr size_t OFF_XGB   = OFF_XGF   + (size_t)2048*2048;   // [2048,2048]
constexpr size_t OFF_HFB   = OFF_XGB   + (size_t)2048*2048;   // [2048,1024]
constexpr size_t OFF_ENC   = OFF_HFB   + (size_t)2048*1024;   // [2048,512]
constexpr size_t OFF_H1    = OFF_ENC   + (size_t)2048*512;    // [2048,512]
constexpr size_t OFF_H2    = OFF_H1    + (size_t)2048*512;    // [2048,256]
constexpr size_t OFF_CNT   = OFF_H2    + (size_t)2048*256;    // [8,256]
constexpr size_t OFF_MELIN = OFF_CNT   + (size_t)8*256;       // [8192,80]
constexpr size_t OFF_K     = OFF_MELIN + (size_t)8192*80;     // [2048,512]
constexpr size_t OFF_V     = OFF_K     + (size_t)2048*512;    // [2048,512]
constexpr size_t OFF_DECIN = OFF_V     + (size_t)2048*512;    // [8192,1024]
constexpr size_t OFF_Q     = OFF_DECIN + (size_t)8192*1024;   // [8192,512]
constexpr size_t OFF_CTX   = OFF_Q     + (size_t)8192*512;    // [8192,512]
constexpr size_t OFF_DXG   = OFF_CTX   + (size_t)8192*512;    // [8192,2048]
constexpr size_t OFF_DOUT  = OFF_DXG   + (size_t)8192*2048;   // [8192,512]
constexpr size_t OFF_HBUF  = OFF_DOUT  + (size_t)8192*512;    // 6*4096
constexpr size_t ARENA_SZ  = OFF_HBUF  + (size_t)6*4096;

__device__ __align__(16) float g_arena[ARENA_SZ];
// one counter per barrier group, each on its own 128B line
__device__ unsigned g_cntarr[3 * 32];

__global__ void reset_bars_kernel() {
    if (threadIdx.x < 3 * 32) g_cntarr[threadIdx.x] = 0u;
}

__global__ void gather_emb_kernel(const int* __restrict__ idx, const float* __restrict__ emb) {
    int bt = blockIdx.x;
    const float4* s = reinterpret_cast<const float4*>(emb + (size_t)idx[bt] * 512);
    float4* d = reinterpret_cast<float4*>(g_arena + OFF_X + (size_t)bt * 512);
    d[threadIdx.x] = __ldg(s + threadIdx.x);
}

__global__ void shift_mel_kernel(const float* __restrict__ mel) {
    int i = blockIdx.x * 256 + threadIdx.x;
    if (i < 8 * 1024 * 80) {
        int t = (i % (1024 * 80)) / 80;
        g_arena[OFF_MELIN + i] = (t == 0) ? 0.f : mel[i - 80];
    }
}

__global__ void counts_kernel(const float* __restrict__ dur) {
    __shared__ int cum[256];
    int b = blockIdx.x, t = threadIdx.x;
    cum[t] = (int)rintf(dur[b * 256 + t]);
    __syncthreads();
    for (int off = 1; off < 256; off <<= 1) {
        int add = (t >= off) ? cum[t - off] : 0;
        __syncthreads();
        cum[t] += add;
        __syncthreads();
    }
    int hi = min(cum[t], 1024);
    int lo = (t > 0) ? min(cum[t - 1], 1024) : 0;
    g_arena[OFF_CNT + b * 256 + t] = (float)(hi - lo);
}

// ---------------- fp32 SGEMM: C[M,N] = A[M,K] @ W[N,K]^T + bias ------------
// 128x128 tile, K-slice 8, double-buffered smem + per-kk fragment pipeline.
template <bool RELU>
__global__ void __launch_bounds__(256) sgemm_kernel(
    const float* __restrict__ A, int lda, const float* __restrict__ W,
    const float* __restrict__ bias, float* __restrict__ C, int ldc,
    int M, int N, int K)
{
    __shared__ float As[2][8][128];
    __shared__ float Bs[2][8][128];
    const int tid = threadIdx.x;
    const int lrow = tid >> 1, lkq = (tid & 1) << 2;
    const int tx = tid & 15, ty = tid >> 4;
    const int mBase = blockIdx.y * 128, nBase = blockIdx.x * 128;
    float acc[8][8];
#pragma unroll
    for (int i = 0; i < 8; i++)
#pragma unroll
        for (int j = 0; j < 8; j++) acc[i][j] = 0.f;
    const int am = mBase + lrow, bn = nBase + lrow;
    const float* aptr = A + (size_t)am * lda + lkq;
    const float* wptr = W + (size_t)bn * K + lkq;

    float4 av = make_float4(0.f, 0.f, 0.f, 0.f), bv = av;
    if (am < M) av = *reinterpret_cast<const float4*>(aptr);
    if (bn < N) bv = *reinterpret_cast<const float4*>(wptr);
    As[0][lkq + 0][lrow] = av.x; As[0][lkq + 1][lrow] = av.y;
    As[0][lkq + 2][lrow] = av.z; As[0][lkq + 3][lrow] = av.w;
    Bs[0][lkq + 0][lrow] = bv.x; Bs[0][lkq + 1][lrow] = bv.y;
    Bs[0][lkq + 2][lrow] = bv.z; Bs[0][lkq + 3][lrow] = bv.w;
    __syncthreads();

    int p = 0;
    for (int k0 = 0; k0 < K; k0 += 8) {
        bool more = (k0 + 8) < K;
        if (more) {
            av = make_float4(0.f, 0.f, 0.f, 0.f); bv = av;
            if (am < M) av = *reinterpret_cast<const float4*>(aptr + k0 + 8);
            if (bn < N) bv = *reinterpret_cast<const float4*>(wptr + k0 + 8);
        }
        // fragment-pipelined inner product over the 8-deep smem slab
        float4 a0 = *reinterpret_cast<const float4*>(&As[p][0][ty * 8]);
        float4 a1 = *reinterpret_cast<const float4*>(&As[p][0][ty * 8 + 4]);
        float4 b0 = *reinterpret_cast<const float4*>(&Bs[p][0][tx * 8]);
        float4 b1 = *reinterpret_cast<const float4*>(&Bs[p][0][tx * 8 + 4]);
#pragma unroll
        for (int kk = 0; kk < 8; kk++) {
            float4 na0, na1, nb0, nb1;
            if (kk < 7) {
                na0 = *reinterpret_cast<const float4*>(&As[p][kk + 1][ty * 8]);
                na1 = *reinterpret_cast<const float4*>(&As[p][kk + 1][ty * 8 + 4]);
                nb0 = *reinterpret_cast<const float4*>(&Bs[p][kk + 1][tx * 8]);
                nb1 = *reinterpret_cast<const float4*>(&Bs[p][kk + 1][tx * 8 + 4]);
            }
            float ar[8] = {a0.x, a0.y, a0.z, a0.w, a1.x, a1.y, a1.z, a1.w};
            float br[8] = {b0.x, b0.y, b0.z, b0.w, b1.x, b1.y, b1.z, b1.w};
#pragma unroll
            for (int i = 0; i < 8; i++)
#pragma unroll
                for (int j = 0; j < 8; j++) acc[i][j] = fmaf(ar[i], br[j], acc[i][j]);
            if (kk < 7) { a0 = na0; a1 = na1; b0 = nb0; b1 = nb1; }
        }
        if (more) {
            int q = p ^ 1;
            As[q][lkq + 0][lrow] = av.x; As[q][lkq + 1][lrow] = av.y;
            As[q][lkq + 2][lrow] = av.z; As[q][lkq + 3][lrow] = av.w;
            Bs[q][lkq + 0][lrow] = bv.x; Bs[q][lkq + 1][lrow] = bv.y;
            Bs[q][lkq + 2][lrow] = bv.z; Bs[q][lkq + 3][lrow] = bv.w;
            __syncthreads();
            p = q;
        }
    }
#pragma unroll
    for (int i = 0; i < 8; i++) {
        int m = mBase + ty * 8 + i;
        if (m >= M) continue;
#pragma unroll
        for (int j = 0; j < 8; j++) {
            int n = nBase + tx * 8 + j;
            if (n >= N) continue;
            float v = acc[i][j] + bias[n];
            if (RELU) v = fmaxf(v, 0.f);
            C[(size_t)m * ldc + n] = v;
        }
    }
}

// ---------------- persistent LSTM recurrence (cluster fan-out) -------------
__device__ __forceinline__ float sigf(float x) { return 1.0f / (1.0f + expf(-x)); }

__device__ __forceinline__ unsigned ld_acq(const unsigned* p) {
    unsigned v;
    asm volatile("ld.acquire.gpu.global.u32 %0, [%1];" : "=r"(v) : "l"(p) : "memory");
    return v;
}
__device__ __forceinline__ void red_rel_add1(unsigned* p) {
    asm volatile("red.release.gpu.global.add.u32 [%0], 1;" :: "l"(p) : "memory");
}
// DSMEM epoch flag: rank0 stores to peer CTA's smem flag (release, cluster)
__device__ __forceinline__ void dsmem_flag_store(unsigned local_addr, unsigned rank, unsigned v) {
    unsigned remote;
    asm volatile("mapa.shared::cluster.u32 %0, %1, %2;"
                 : "=r"(remote) : "r"(local_addr), "r"(rank));
    asm volatile("st.release.cluster.shared::cluster.u32 [%0], %1;"
                 :: "r"(remote), "r"(v) : "memory");
}
__device__ __forceinline__ unsigned smem_flag_ld(unsigned addr) {
    unsigned v;
    asm volatile("ld.acquire.cluster.shared::cta.u32 %0, [%1];"
                 : "=r"(v) : "r"(addr) : "memory");
    return v;
}

// arrive: all prior CTA writes happen-before (bar.sync) the release RED
__device__ __forceinline__ void bar_arrive(unsigned* cnt) {
    __syncthreads();
    if (threadIdx.x == 0) red_rel_add1(cnt);
}

// JPC hidden units per CTA, KCN k-chunks; 4*JPC*KCN == 256 threads
// Grid layout: cluster dims (8,1,1); rank = blockIdx.x (cluster-local).
template <int JPC, int KCN>
__device__ __forceinline__ void lstm_core(
    const float* __restrict__ xg, const float* __restrict__ W,
    const float* __restrict__ bhh, float* __restrict__ out,
    int outStride, int outOffset, float* hbuf,
    unsigned* cnt, int T, bool reverse, int rcta, unsigned nCTA)
{
    constexpr int GPC = 4 * JPC;
    constexpr int CHUNK = 512 / KCN;
    constexpr int PP = 9;               // padded stride: conflict-free STS
    const int tid = threadIdx.x;
    const int g_local = tid % GPC, kc = tid / GPC;
    const int type = g_local & 3, j_loc = g_local >> 2;
    const int gate_g = type * 512 + rcta * JPC + j_loc;

    float w[CHUNK];
    {
        const float4* wp = reinterpret_cast<const float4*>(W + (size_t)gate_g * 512 + kc * CHUNK);
#pragma unroll
        for (int i = 0; i < CHUNK / 4; i++) {
            float4 t4 = __ldg(wp + i);
            w[4*i] = t4.x; w[4*i+1] = t4.y; w[4*i+2] = t4.z; w[4*i+3] = t4.w;
        }
    }

    int red_g = tid >> 3, red_b = tid & 7;
    int red_gg = (red_g & 3) * 512 + rcta * JPC + (red_g >> 2);
    float bconst = (tid < GPC * 8) ? __ldg(bhh + red_gg) : 0.f;

    __shared__ float h_sm[8 * 512];
    __shared__ float partial[256 * PP];
    __shared__ float gsm[GPC * 8];
    __shared__ float c_sm[JPC * 8];
    __shared__ unsigned flag_sm;

    const unsigned flag_addr = (unsigned)__cvta_generic_to_shared(&flag_sm);
    if (tid == 0) flag_sm = 0u;

    if (tid < JPC * 8) {
        c_sm[tid] = 0.f;
        int jl = tid >> 3, b = tid & 7;
        __stcg(hbuf + b * 512 + rcta * JPC + jl, 0.f);
    }
    bar_arrive(cnt);   // also orders the flag_sm init before any peer write

    unsigned epoch = nCTA;
    for (int s = 0; s < T; s++) {
        const int t = reverse ? (T - 1 - s) : s;
        // prefetch this step's xg gate value BEFORE the barrier wait
        float xval = 0.f;
        if (tid < GPC * 8)
            xval = __ldg(xg + ((size_t)red_b * T + t) * 2048 + red_gg) + bconst;

        // two-level wait: 8 rank0 pollers on L2 counter, DSMEM fan-out to peers
        const unsigned ep_small = (unsigned)(s + 1);
        if (blockIdx.x == 0) {
            if (tid == 0) {
                while (ld_acq(cnt) < epoch) { }
            }
            __syncwarp();
            if (tid < 8) dsmem_flag_store(flag_addr, tid, ep_small);
        }
        if (tid == 0) {
            while (smem_flag_ld(flag_addr) < ep_small) { }
        }
        __syncthreads();

        {
            const float4* hb4 = reinterpret_cast<const float4*>(hbuf + (s & 1) * 4096);
            float4* hs4 = reinterpret_cast<float4*>(h_sm);
            for (int i = tid; i < 1024; i += 256) hs4[i] = __ldcg(hb4 + i);
        }
        __syncthreads();
#pragma unroll
        for (int b = 0; b < 8; b++) {
            const float* hp = h_sm + b * 512 + kc * CHUNK;
            float a = 0.f;
#pragma unroll
            for (int i = 0; i < CHUNK; i += 4) {
                float4 h4 = *reinterpret_cast<const float4*>(hp + i);
                a = fmaf(h4.x, w[i], a);   a = fmaf(h4.y, w[i+1], a);
                a = fmaf(h4.z, w[i+2], a); a = fmaf(h4.w, w[i+3], a);
            }
            partial[tid * PP + b] = a;
        }
        __syncthreads();
        if (tid < GPC * 8) {
            float acc = xval;
#pragma unroll
            for (int q = 0; q < KCN; q++) acc += partial[(q * GPC + red_g) * PP + red_b];
            gsm[red_g * 8 + red_b] = acc;
        }
        __syncthreads();
        if (tid < JPC * 8) {
            int jl = tid >> 3, b = tid & 7;
            float gi = gsm[(jl * 4 + 0) * 8 + b];
            float gf = gsm[(jl * 4 + 1) * 8 + b];
            float gc = gsm[(jl * 4 + 2) * 8 + b];
            float go = gsm[(jl * 4 + 3) * 8 + b];
            float c = sigf(gf) * c_sm[tid] + sigf(gi) * tanhf(gc);
            float hv = sigf(go) * tanhf(c);
            c_sm[tid] = c;
            int j2 = rcta * JPC + jl;
            __stcg(hbuf + ((s + 1) & 1) * 4096 + b * 512 + j2, hv);
            out[((size_t)b * T + t) * outStride + outOffset + j2] = hv;
        }
        bar_arrive(cnt);
        epoch += nCTA;
    }
}

// encoder: grid (8,16), clusters of 8 along x. y<8 = forward, y>=8 = backward.
__global__ void __launch_bounds__(256) __cluster_dims__(8, 1, 1) enc_lstm_kernel(
    const float* __restrict__ Wf, const float* __restrict__ Wb,
    const float* __restrict__ bf, const float* __restrict__ bb)
{
    int group = blockIdx.y >> 3;
    int rcta  = (blockIdx.y & 7) * 8 + blockIdx.x;
    float* hfb = g_arena + OFF_HFB;
    float* hbuf = g_arena + OFF_HBUF + (size_t)group * 2 * 4096;
    unsigned* cnt = g_cntarr + group * 32;
    if (group == 0)
        lstm_core<8, 8>(g_arena + OFF_XGF, Wf, bf, hfb, 1024, 0, hbuf,
                        cnt, 256, false, rcta, 64u);
    else
        lstm_core<8, 8>(g_arena + OFF_XGB, Wb, bb, hfb, 1024, 512, hbuf,
                        cnt, 256, true, rcta, 64u);
}

// decoder: grid (8,8), one 64-CTA group of 8 clusters
__global__ void __launch_bounds__(256) __cluster_dims__(8, 1, 1) dec_lstm_kernel(
    const float* __restrict__ Whh, const float* __restrict__ bhh)
{
    int rcta = blockIdx.y * 8 + blockIdx.x;
    lstm_core<8, 8>(g_arena + OFF_DXG, Whh, bhh, g_arena + OFF_DOUT, 512, 0,
                    g_arena + OFF_HBUF + (size_t)4 * 4096,
                    g_cntarr + 2 * 32, 1024, false, rcta, 64u);
}

// ---------------- multiplicity-compressed attention ------------------------
extern __shared__ float sm_attn[];
__global__ void __launch_bounds__(256) attn_kernel()
{
    float* ksm = sm_attn;
    float* vsm = sm_attn + 256 * 64;
    __shared__ float csm[256];
    const int tid = threadIdx.x, bid = blockIdx.x;
    const int qc = bid & 3, h = (bid >> 2) & 7, b = bid >> 5;
    {
        const float4* ks = reinterpret_cast<const float4*>(
            g_arena + OFF_K + ((size_t)b * 256 + tid) * 512 + h * 64);
        const float4* vs = reinterpret_cast<const float4*>(
            g_arena + OFF_V + ((size_t)b * 256 + tid) * 512 + h * 64);
        float4* kd = reinterpret_cast<float4*>(ksm + tid * 64);
        float4* vd = reinterpret_cast<float4*>(vsm + tid * 64);
#pragma unroll
        for (int i = 0; i < 16; i++) { kd[i] = __ldg(ks + i); vd[i] = __ldg(vs + i); }
        csm[tid] = g_arena[OFF_CNT + b * 256 + tid];
    }
    __syncthreads();
    const int qi = qc * 256 + tid;
    float qr[64], acc[64];
    {
        const float4* qs = reinterpret_cast<const float4*>(
            g_arena + OFF_Q + ((size_t)b * 1024 + qi) * 512 + h * 64);
#pragma unroll
        for (int i = 0; i < 16; i++) {
            float4 t4 = __ldg(qs + i);
            qr[4*i] = t4.x; qr[4*i+1] = t4.y; qr[4*i+2] = t4.z; qr[4*i+3] = t4.w;
        }
    }
#pragma unroll
    for (int d = 0; d < 64; d++) acc[d] = 0.f;
    float m = -1e30f, l = 0.f;
    for (int j = 0; j < 256; j++) {
        float c = csm[j];
        if (c == 0.f) continue;   // exact: pad keys get weight expf(-1e9-m)==0
        const float4* kr = reinterpret_cast<const float4*>(ksm + j * 64);
        float s = 0.f;
#pragma unroll
        for (int i = 0; i < 16; i++) {
            float4 k4 = kr[i];
            s = fmaf(qr[4*i], k4.x, s);   s = fmaf(qr[4*i+1], k4.y, s);
            s = fmaf(qr[4*i+2], k4.z, s); s = fmaf(qr[4*i+3], k4.w, s);
        }
        s *= 0.125f;
        float wgt;
        if (s > m) {
            float corr = __expf(m - s);
            l *= corr;
#pragma unroll
            for (int d = 0; d < 64; d++) acc[d] *= corr;
            m = s; wgt = c;
        } else {
            wgt = c * __expf(s - m);
        }
        l += wgt;
        const float4* vr = reinterpret_cast<const float4*>(vsm + j * 64);
#pragma unroll
        for (int i = 0; i < 16; i++) {
            float4 v4 = vr[i];
            acc[4*i]   = fmaf(wgt, v4.x, acc[4*i]);
            acc[4*i+1] = fmaf(wgt, v4.y, acc[4*i+1]);
            acc[4*i+2] = fmaf(wgt, v4.z, acc[4*i+2]);
            acc[4*i+3] = fmaf(wgt, v4.w, acc[4*i+3]);
        }
    }
    float inv = 1.0f / l;
    float4* cd = reinterpret_cast<float4*>(
        g_arena + OFF_CTX + ((size_t)b * 1024 + qi) * 512 + h * 64);
#pragma unroll
    for (int i = 0; i < 16; i++)
        cd[i] = make_float4(acc[4*i] * inv, acc[4*i+1] * inv,
                            acc[4*i+2] * inv, acc[4*i+3] * inv);
}

__global__ void logdur_kernel(const float* __restrict__ w3,
                              const float* __restrict__ b3, float* __restrict__ out) {
    int i = blockIdx.x * 256 + threadIdx.x;   // 2048 rows
    const float* h2 = g_arena + OFF_H2 + (size_t)i * 256;
    float s = b3[0];
    for (int k = 0; k < 256; k += 4) {
        float4 a = *reinterpret_cast<const float4*>(h2 + k);
        float4 w = __ldg(reinterpret_cast<const float4*>(w3 + k));
        s = fmaf(a.x, w.x, s); s = fmaf(a.y, w.y, s);
        s = fmaf(a.z, w.z, s); s = fmaf(a.w, w.w, s);
    }
    out[i] = s;
}

// ---------------------------------------------------------------------------
static inline void run_sgemm(const float* A, int lda, const float* W,
                             const float* bias, float* C, int ldc,
                             int M, int N, int K, bool relu = false) {
    dim3 grid((N + 127) / 128, (M + 127) / 128);
    if (relu) sgemm_kernel<true><<<grid, 256>>>(A, lda, W, bias, C, ldc, M, N, K);
    else      sgemm_kernel<false><<<grid, 256>>>(A, lda, W, bias, C, ldc, M, N, K);
}

extern "C" void kernel_launch(void* const* d_in, const int* in_sizes, int n_in,
                              void* d_out, int out_size) {
    const int*   ph   = (const int*)  d_in[0];
    const float* mel  = (const float*)d_in[1];
    const float* dur  = (const float*)d_in[2];
    const float* emb  = (const float*)d_in[3];
    const float* ewif = (const float*)d_in[4];
    const float* ewhf = (const float*)d_in[5];
    const float* ebif = (const float*)d_in[6];
    const float* ebhf = (const float*)d_in[7];
    const float* ewib = (const float*)d_in[8];
    const float* ewhb = (const float*)d_in[9];
    const float* ebib = (const float*)d_in[10];
    const float* ebhb = (const float*)d_in[11];
    const float* projw = (const float*)d_in[12];
    const float* projb = (const float*)d_in[13];
    const float* dw1 = (const float*)d_in[14];
    const float* db1 = (const float*)d_in[15];
    const float* dw2 = (const float*)d_in[16];
    const float* db2 = (const float*)d_in[17];
    const float* dw3 = (const float*)d_in[18];
    const float* db3 = (const float*)d_in[19];
    const float* miw = (const float*)d_in[20];
    const float* mib = (const float*)d_in[21];
    const float* aiw = (const float*)d_in[22];
    const float* aib = (const float*)d_in[23];
    const float* aow = (const float*)d_in[24];
    const float* aob = (const float*)d_in[25];
    const float* dwih = (const float*)d_in[26];
    const float* dwhh = (const float*)d_in[27];
    const float* dbih = (const float*)d_in[28];
    const float* dbhh = (const float*)d_in[29];
    const float* mow = (const float*)d_in[30];
    const float* mob = (const float*)d_in[31];
    float* out = (float*)d_out;

    float* A;
    cudaGetSymbolAddress((void**)&A, g_arena);

    reset_bars_kernel<<<1, 128>>>();
    gather_emb_kernel<<<2048, 128>>>(ph, emb);
    // encoder input-gate precompute (includes b_ih)
    run_sgemm(A + OFF_X, 512, ewif, ebif, A + OFF_XGF, 2048, 2048, 2048, 512);
    run_sgemm(A + OFF_X, 512, ewib, ebib, A + OFF_XGB, 2048, 2048, 2048, 512);
    enc_lstm_kernel<<<dim3(8, 16), 256>>>(ewhf, ewhb, ebhf, ebhb);
    run_sgemm(A + OFF_HFB, 1024, projw, projb, A + OFF_ENC, 512, 2048, 512, 1024);
    // duration predictor
    run_sgemm(A + OFF_ENC, 512, dw1, db1, A + OFF_H1, 512, 2048, 512, 512, true);
    run_sgemm(A + OFF_H1, 512, dw2, db2, A + OFF_H2, 256, 2048, 256, 512, true);
    logdur_kernel<<<8, 256>>>(dw3, db3, out + (size_t)8 * 1024 * 80);
    // attention path
    counts_kernel<<<8, 256>>>(dur);
    shift_mel_kernel<<<2560, 256>>>(mel);
    run_sgemm(A + OFF_MELIN, 80, miw, mib, A + OFF_DECIN, 1024, 8192, 512, 80); // q_in
    run_sgemm(A + OFF_DECIN, 1024, aiw, aib, A + OFF_Q, 512, 8192, 512, 512);  // Q
    run_sgemm(A + OFF_ENC, 512, aiw + (size_t)512 * 512, aib + 512,
              A + OFF_K, 512, 2048, 512, 512);                                  // K
    run_sgemm(A + OFF_ENC, 512, aiw + (size_t)1024 * 512, aib + 1024,
              A + OFF_V, 512, 2048, 512, 512);                                  // V
    cudaFuncSetAttribute(attn_kernel, cudaFuncAttributeMaxDynamicSharedMemorySize,
                         2 * 256 * 64 * (int)sizeof(float));
    attn_kernel<<<256, 256, 2 * 256 * 64 * sizeof(float)>>>();
    run_sgemm(A + OFF_CTX, 512, aow, aob, A + OFF_DECIN + 512, 1024,
              8192, 512, 512);                                                  // attended
    // decoder
    run_sgemm(A + OFF_DECIN, 1024, dwih, dbih, A + OFF_DXG, 2048,
              8192, 2048, 1024);
    dec_lstm_kernel<<<dim3(8, 8), 256>>>(dwhh, dbhh);
    run_sgemm(A + OFF_DOUT, 512, mow, mob, out, 80, 8192, 80, 512);             // mel_pred
}

// round 16
// speedup vs baseline: 1.1199x; 1.1199x over previous
#include <cuda_runtime.h>
#include <cuda_bf16.h>
#include <math.h>

// dims: B=8, T_TEXT=256, T_MEL=1024, VOCAB=256, MEL=80, H=512, NH=8, HD=64

// ------------------------- scratch arena -----------------------------------
constexpr size_t OFF_X     = 0;                               // [2048,512]
constexpr size_t OFF_XGF   = OFF_X     + (size_t)2048*512;    // [2048,2048]
constexpr size_t OFF_XGB   = OFF_XGF   + (size_t)2048*2048;   // [2048,2048]
constexpr size_t OFF_HFB   = OFF_XGB   + (size_t)2048*2048;   // [2048,1024]
constexpr size_t OFF_ENC   = OFF_HFB   + (size_t)2048*1024;   // [2048,512]
constexpr size_t OFF_H1    = OFF_ENC   + (size_t)2048*512;    // [2048,512]
constexpr size_t OFF_H2    = OFF_H1    + (size_t)2048*512;    // [2048,256]
constexpr size_t OFF_CNT   = OFF_H2    + (size_t)2048*256;    // [8,256]
constexpr size_t OFF_MELIN = OFF_CNT   + (size_t)8*256;       // [8192,80]
constexpr size_t OFF_K     = OFF_MELIN + (size_t)8192*80;     // [2048,512]
constexpr size_t OFF_V     = OFF_K     + (size_t)2048*512;    // [2048,512]
constexpr size_t OFF_DECIN = OFF_V     + (size_t)2048*512;    // [8192,1024]
constexpr size_t OFF_Q     = OFF_DECIN + (size_t)8192*1024;   // [8192,512]
constexpr size_t OFF_CTX   = OFF_Q     + (size_t)8192*512;    // [8192,512]
constexpr size_t OFF_DXG   = OFF_CTX   + (size_t)8192*512;    // [8192,2048]
constexpr size_t OFF_DOUT  = OFF_DXG   + (size_t)8192*2048;   // [8192,512]
constexpr size_t OFF_HBUF  = OFF_DOUT  + (size_t)8192*512;    // 6*4096
constexpr size_t ARENA_SZ  = OFF_HBUF  + (size_t)6*4096;

__device__ __align__(16) float g_arena[ARENA_SZ];
// striped barrier counters: 3 groups x 8 lines x 32 words (one line each)
__device__ unsigned g_cntarr[3 * 8 * 32];

__global__ void reset_bars_kernel() {
    int i = blockIdx.x * 256 + threadIdx.x;
    if (i < 3 * 8 * 32) g_cntarr[i] = 0u;
}

__global__ void gather_emb_kernel(const int* __restrict__ idx, const float* __restrict__ emb) {
    int bt = blockIdx.x;
    const float4* s = reinterpret_cast<const float4*>(emb + (size_t)idx[bt] * 512);
    float4* d = reinterpret_cast<float4*>(g_arena + OFF_X + (size_t)bt * 512);
    d[threadIdx.x] = __ldg(s + threadIdx.x);
}

__global__ void shift_mel_kernel(const float* __restrict__ mel) {
    int i = blockIdx.x * 256 + threadIdx.x;
    if (i < 8 * 1024 * 80) {
        int t = (i % (1024 * 80)) / 80;
        g_arena[OFF_MELIN + i] = (t == 0) ? 0.f : mel[i - 80];
    }
}

__global__ void counts_kernel(const float* __restrict__ dur) {
    __shared__ int cum[256];
    int b = blockIdx.x, t = threadIdx.x;
    cum[t] = (int)rintf(dur[b * 256 + t]);
    __syncthreads();
    for (int off = 1; off < 256; off <<= 1) {
        int add = (t >= off) ? cum[t - off] : 0;
        __syncthreads();
        cum[t] += add;
        __syncthreads();
    }
    int hi = min(cum[t], 1024);
    int lo = (t > 0) ? min(cum[t - 1], 1024) : 0;
    g_arena[OFF_CNT + b * 256 + t] = (float)(hi - lo);
}

// ---------------- fp32 SGEMM: C[M,N] = A[M,K] @ W[N,K]^T + bias ------------
// 128x128 tile, K-slice 8, double-buffered smem + per-kk fragment pipeline.
template <bool RELU>
__global__ void __launch_bounds__(256) sgemm_kernel(
    const float* __restrict__ A, int lda, const float* __restrict__ W,
    const float* __restrict__ bias, float* __restrict__ C, int ldc,
    int M, int N, int K)
{
    __shared__ float As[2][8][128];
    __shared__ float Bs[2][8][128];
    const int tid = threadIdx.x;
    const int lrow = tid >> 1, lkq = (tid & 1) << 2;
    const int tx = tid & 15, ty = tid >> 4;
    const int mBase = blockIdx.y * 128, nBase = blockIdx.x * 128;
    float acc[8][8];
#pragma unroll
    for (int i = 0; i < 8; i++)
#pragma unroll
        for (int j = 0; j < 8; j++) acc[i][j] = 0.f;
    const int am = mBase + lrow, bn = nBase + lrow;
    const float* aptr = A + (size_t)am * lda + lkq;
    const float* wptr = W + (size_t)bn * K + lkq;

    float4 av = make_float4(0.f, 0.f, 0.f, 0.f), bv = av;
    if (am < M) av = *reinterpret_cast<const float4*>(aptr);
    if (bn < N) bv = *reinterpret_cast<const float4*>(wptr);
    As[0][lkq + 0][lrow] = av.x; As[0][lkq + 1][lrow] = av.y;
    As[0][lkq + 2][lrow] = av.z; As[0][lkq + 3][lrow] = av.w;
    Bs[0][lkq + 0][lrow] = bv.x; Bs[0][lkq + 1][lrow] = bv.y;
    Bs[0][lkq + 2][lrow] = bv.z; Bs[0][lkq + 3][lrow] = bv.w;
    __syncthreads();

    int p = 0;
    for (int k0 = 0; k0 < K; k0 += 8) {
        bool more = (k0 + 8) < K;
        if (more) {
            av = make_float4(0.f, 0.f, 0.f, 0.f); bv = av;
            if (am < M) av = *reinterpret_cast<const float4*>(aptr + k0 + 8);
            if (bn < N) bv = *reinterpret_cast<const float4*>(wptr + k0 + 8);
        }
        float4 a0 = *reinterpret_cast<const float4*>(&As[p][0][ty * 8]);
        float4 a1 = *reinterpret_cast<const float4*>(&As[p][0][ty * 8 + 4]);
        float4 b0 = *reinterpret_cast<const float4*>(&Bs[p][0][tx * 8]);
        float4 b1 = *reinterpret_cast<const float4*>(&Bs[p][0][tx * 8 + 4]);
#pragma unroll
        for (int kk = 0; kk < 8; kk++) {
            float4 na0, na1, nb0, nb1;
            if (kk < 7) {
                na0 = *reinterpret_cast<const float4*>(&As[p][kk + 1][ty * 8]);
                na1 = *reinterpret_cast<const float4*>(&As[p][kk + 1][ty * 8 + 4]);
                nb0 = *reinterpret_cast<const float4*>(&Bs[p][kk + 1][tx * 8]);
                nb1 = *reinterpret_cast<const float4*>(&Bs[p][kk + 1][tx * 8 + 4]);
            }
            float ar[8] = {a0.x, a0.y, a0.z, a0.w, a1.x, a1.y, a1.z, a1.w};
            float br[8] = {b0.x, b0.y, b0.z, b0.w, b1.x, b1.y, b1.z, b1.w};
#pragma unroll
            for (int i = 0; i < 8; i++)
#pragma unroll
                for (int j = 0; j < 8; j++) acc[i][j] = fmaf(ar[i], br[j], acc[i][j]);
            if (kk < 7) { a0 = na0; a1 = na1; b0 = nb0; b1 = nb1; }
        }
        if (more) {
            int q = p ^ 1;
            As[q][lkq + 0][lrow] = av.x; As[q][lkq + 1][lrow] = av.y;
            As[q][lkq + 2][lrow] = av.z; As[q][lkq + 3][lrow] = av.w;
            Bs[q][lkq + 0][lrow] = bv.x; Bs[q][lkq + 1][lrow] = bv.y;
            Bs[q][lkq + 2][lrow] = bv.z; Bs[q][lkq + 3][lrow] = bv.w;
            __syncthreads();
            p = q;
        }
    }
#pragma unroll
    for (int i = 0; i < 8; i++) {
        int m = mBase + ty * 8 + i;
        if (m >= M) continue;
#pragma unroll
        for (int j = 0; j < 8; j++) {
            int n = nBase + tx * 8 + j;
            if (n >= N) continue;
            float v = acc[i][j] + bias[n];
            if (RELU) v = fmaxf(v, 0.f);
            C[(size_t)m * ldc + n] = v;
        }
    }
}

// ---------------- persistent LSTM recurrence -------------------------------
__device__ __forceinline__ float sigf(float x) { return 1.0f / (1.0f + expf(-x)); }

__device__ __forceinline__ unsigned ld_rlx(const unsigned* p) {
    unsigned v;
    asm volatile("ld.relaxed.gpu.global.u32 %0, [%1];" : "=r"(v) : "l"(p) : "memory");
    return v;
}
__device__ __forceinline__ void red_rel_add1(unsigned* p) {
    asm volatile("red.release.gpu.global.add.u32 [%0], 1;" :: "l"(p) : "memory");
}
__device__ __forceinline__ void fence_acqrel() {
    asm volatile("fence.acq_rel.gpu;" ::: "memory");
}

// arrive: prior CTA writes happen-before (bar.sync) the release RED on this
// CTA's stripe line (8 lines per group -> parallel L2 atomic fan-in)
__device__ __forceinline__ void bar_arrive(unsigned* cnt, int rcta) {
    __syncthreads();
    if (threadIdx.x == 0) red_rel_add1(cnt + (rcta & 7) * 32);
}
// wait: thread 0 spins with relaxed pipelined loads over all 8 stripe lines;
// one acq_rel fence after the condition pairs with all release-REDs.
__device__ __forceinline__ void bar_wait(unsigned* cnt, unsigned per_line_target) {
    if (threadIdx.x == 0) {
        for (;;) {
            bool done = true;
#pragma unroll
            for (int i = 0; i < 8; i++)
                if (ld_rlx(cnt + i * 32) < per_line_target) done = false;
            if (done) break;
        }
        fence_acqrel();
    }
    __syncthreads();
}

// JPC hidden units per CTA, KCN k-chunks; 4*JPC*KCN == 256 threads
template <int JPC, int KCN>
__device__ __forceinline__ void lstm_core(
    const float* __restrict__ xg, const float* __restrict__ W,
    const float* __restrict__ bhh, float* __restrict__ out,
    int outStride, int outOffset, float* hbuf,
    unsigned* cnt, int T, bool reverse, int rcta, unsigned nCTA)
{
    constexpr int GPC = 4 * JPC;
    constexpr int CHUNK = 512 / KCN;
    const int tid = threadIdx.x;
    const int g_local = tid % GPC, kc = tid / GPC;
    const int type = g_local & 3, j_loc = g_local >> 2;
    const int gate_g = type * 512 + rcta * JPC + j_loc;

    float w[CHUNK];
    {
        const float4* wp = reinterpret_cast<const float4*>(W + (size_t)gate_g * 512 + kc * CHUNK);
#pragma unroll
        for (int i = 0; i < CHUNK / 4; i++) {
            float4 t4 = __ldg(wp + i);
            w[4*i] = t4.x; w[4*i+1] = t4.y; w[4*i+2] = t4.z; w[4*i+3] = t4.w;
        }
    }

    int red_g = tid >> 3, red_b = tid & 7;
    int red_gg = (red_g & 3) * 512 + rcta * JPC + (red_g >> 2);
    float bconst = (tid < GPC * 8) ? __ldg(bhh + red_gg) : 0.f;

    __shared__ float h_sm[8 * 512];
    __shared__ float partial[256 * 8];
    __shared__ float gsm[GPC * 8];
    __shared__ float c_sm[JPC * 8];

    if (tid < JPC * 8) {
        c_sm[tid] = 0.f;
        int jl = tid >> 3, b = tid & 7;
        __stcg(hbuf + b * 512 + rcta * JPC + jl, 0.f);
    }
    bar_arrive(cnt, rcta);

    const unsigned perLine = nCTA >> 3;
    for (int s = 0; s < T; s++) {
        const int t = reverse ? (T - 1 - s) : s;
        // prefetch this step's xg gate value BEFORE the barrier wait
        float xval = 0.f;
        if (tid < GPC * 8)
            xval = __ldg(xg + ((size_t)red_b * T + t) * 2048 + red_gg) + bconst;

        bar_wait(cnt, (unsigned)(s + 1) * perLine);
        {
            const float4* hb4 = reinterpret_cast<const float4*>(hbuf + (s & 1) * 4096);
            float4* hs4 = reinterpret_cast<float4*>(h_sm);
            for (int i = tid; i < 1024; i += 256) hs4[i] = __ldcg(hb4 + i);
        }
        __syncthreads();
#pragma unroll
        for (int b = 0; b < 8; b++) {
            const float* hp = h_sm + b * 512 + kc * CHUNK;
            float a = 0.f;
#pragma unroll
            for (int i = 0; i < CHUNK; i += 4) {
                float4 h4 = *reinterpret_cast<const float4*>(hp + i);
                a = fmaf(h4.x, w[i], a);   a = fmaf(h4.y, w[i+1], a);
                a = fmaf(h4.z, w[i+2], a); a = fmaf(h4.w, w[i+3], a);
            }
            partial[(kc * GPC + g_local) * 8 + b] = a;
        }
        __syncthreads();
        if (tid < GPC * 8) {
            float acc = xval;
#pragma unroll
            for (int q = 0; q < KCN; q++) acc += partial[(q * GPC + red_g) * 8 + red_b];
            gsm[red_g * 8 + red_b] = acc;
        }
        __syncthreads();
        if (tid < JPC * 8) {
            int jl = tid >> 3, b = tid & 7;
            float gi = gsm[(jl * 4 + 0) * 8 + b];
            float gf = gsm[(jl * 4 + 1) * 8 + b];
            float gc = gsm[(jl * 4 + 2) * 8 + b];
            float go = gsm[(jl * 4 + 3) * 8 + b];
            float c = sigf(gf) * c_sm[tid] + sigf(gi) * tanhf(gc);
            float hv = sigf(go) * tanhf(c);
            c_sm[tid] = c;
            int j2 = rcta * JPC + jl;
            __stcg(hbuf + ((s + 1) & 1) * 4096 + b * 512 + j2, hv);
            out[((size_t)b * T + t) * outStride + outOffset + j2] = hv;
        }
        bar_arrive(cnt, rcta);
    }
}

__global__ void __launch_bounds__(256) enc_lstm_kernel(
    const float* __restrict__ Wf, const float* __restrict__ Wb,
    const float* __restrict__ bf, const float* __restrict__ bb)
{
    int group = blockIdx.x >> 6, rcta = blockIdx.x & 63;
    float* hfb = g_arena + OFF_HFB;
    float* hbuf = g_arena + OFF_HBUF + (size_t)group * 2 * 4096;
    unsigned* cnt = g_cntarr + group * 8 * 32;
    if (group == 0)
        lstm_core<8, 8>(g_arena + OFF_XGF, Wf, bf, hfb, 1024, 0, hbuf,
                        cnt, 256, false, rcta, 64u);
    else
        lstm_core<8, 8>(g_arena + OFF_XGB, Wb, bb, hfb, 1024, 512, hbuf,
                        cnt, 256, true, rcta, 64u);
}

// decoder: 128 CTAs, 4 hidden units each (R10 config) + striped barrier
__global__ void __launch_bounds__(256) dec_lstm_kernel(
    const float* __restrict__ Whh, const float* __restrict__ bhh)
{
    lstm_core<4, 16>(g_arena + OFF_DXG, Whh, bhh, g_arena + OFF_DOUT, 512, 0,
                     g_arena + OFF_HBUF + (size_t)4 * 4096,
                     g_cntarr + 2 * 8 * 32, 1024, false, blockIdx.x, 128u);
}

// ---------------- multiplicity-compressed attention ------------------------
extern __shared__ float sm_attn[];
__global__ void __launch_bounds__(256) attn_kernel()
{
    float* ksm = sm_attn;
    float* vsm = sm_attn + 256 * 64;
    __shared__ float csm[256];
    const int tid = threadIdx.x, bid = blockIdx.x;
    const int qc = bid & 3, h = (bid >> 2) & 7, b = bid >> 5;
    {
        const float4* ks = reinterpret_cast<const float4*>(
            g_arena + OFF_K + ((size_t)b * 256 + tid) * 512 + h * 64);
        const float4* vs = reinterpret_cast<const float4*>(
            g_arena + OFF_V + ((size_t)b * 256 + tid) * 512 + h * 64);
        float4* kd = reinterpret_cast<float4*>(ksm + tid * 64);
        float4* vd = reinterpret_cast<float4*>(vsm + tid * 64);
#pragma unroll
        for (int i = 0; i < 16; i++) { kd[i] = __ldg(ks + i); vd[i] = __ldg(vs + i); }
        csm[tid] = g_arena[OFF_CNT + b * 256 + tid];
    }
    __syncthreads();
    const int qi = qc * 256 + tid;
    float qr[64], acc[64];
    {
        const float4* qs = reinterpret_cast<const float4*>(
            g_arena + OFF_Q + ((size_t)b * 1024 + qi) * 512 + h * 64);
#pragma unroll
        for (int i = 0; i < 16; i++) {
            float4 t4 = __ldg(qs + i);
            qr[4*i] = t4.x; qr[4*i+1] = t4.y; qr[4*i+2] = t4.z; qr[4*i+3] = t4.w;
        }
    }
#pragma unroll
    for (int d = 0; d < 64; d++) acc[d] = 0.f;
    float m = -1e30f, l = 0.f;
    for (int j = 0; j < 256; j++) {
        float c = csm[j];
        if (c == 0.f) continue;   // exact: pad keys get weight expf(-1e9-m)==0
        const float4* kr = reinterpret_cast<const float4*>(ksm + j * 64);
        float s = 0.f;
#pragma unroll
        for (int i = 0; i < 16; i++) {
            float4 k4 = kr[i];
            s = fmaf(qr[4*i], k4.x, s);   s = fmaf(qr[4*i+1], k4.y, s);
            s = fmaf(qr[4*i+2], k4.z, s); s = fmaf(qr[4*i+3], k4.w, s);
        }
        s *= 0.125f;
        float wgt;
        if (s > m) {
            float corr = __expf(m - s);
            l *= corr;
#pragma unroll
            for (int d = 0; d < 64; d++) acc[d] *= corr;
            m = s; wgt = c;
        } else {
            wgt = c * __expf(s - m);
        }
        l += wgt;
        const float4* vr = reinterpret_cast<const float4*>(vsm + j * 64);
#pragma unroll
        for (int i = 0; i < 16; i++) {
            float4 v4 = vr[i];
            acc[4*i]   = fmaf(wgt, v4.x, acc[4*i]);
            acc[4*i+1] = fmaf(wgt, v4.y, acc[4*i+1]);
            acc[4*i+2] = fmaf(wgt, v4.z, acc[4*i+2]);
            acc[4*i+3] = fmaf(wgt, v4.w, acc[4*i+3]);
        }
    }
    float inv = 1.0f / l;
    float4* cd = reinterpret_cast<float4*>(
        g_arena + OFF_CTX + ((size_t)b * 1024 + qi) * 512 + h * 64);
#pragma unroll
    for (int i = 0; i < 16; i++)
        cd[i] = make_float4(acc[4*i] * inv, acc[4*i+1] * inv,
                            acc[4*i+2] * inv, acc[4*i+3] * inv);
}

__global__ void logdur_kernel(const float* __restrict__ w3,
                              const float* __restrict__ b3, float* __restrict__ out) {
    int i = blockIdx.x * 256 + threadIdx.x;   // 2048 rows
    const float* h2 = g_arena + OFF_H2 + (size_t)i * 256;
    float s = b3[0];
    for (int k = 0; k < 256; k += 4) {
        float4 a = *reinterpret_cast<const float4*>(h2 + k);
        float4 w = __ldg(reinterpret_cast<const float4*>(w3 + k));
        s = fmaf(a.x, w.x, s); s = fmaf(a.y, w.y, s);
        s = fmaf(a.z, w.z, s); s = fmaf(a.w, w.w, s);
    }
    out[i] = s;
}

// ---------------------------------------------------------------------------
static inline void run_sgemm(const float* A, int lda, const float* W,
                             const float* bias, float* C, int ldc,
                             int M, int N, int K, bool relu = false) {
    dim3 grid((N + 127) / 128, (M + 127) / 128);
    if (relu) sgemm_kernel<true><<<grid, 256>>>(A, lda, W, bias, C, ldc, M, N, K);
    else      sgemm_kernel<false><<<grid, 256>>>(A, lda, W, bias, C, ldc, M, N, K);
}

extern "C" void kernel_launch(void* const* d_in, const int* in_sizes, int n_in,
                              void* d_out, int out_size) {
    const int*   ph   = (const int*)  d_in[0];
    const float* mel  = (const float*)d_in[1];
    const float* dur  = (const float*)d_in[2];
    const float* emb  = (const float*)d_in[3];
    const float* ewif = (const float*)d_in[4];
    const float* ewhf = (const float*)d_in[5];
    const float* ebif = (const float*)d_in[6];
    const float* ebhf = (const float*)d_in[7];
    const float* ewib = (const float*)d_in[8];
    const float* ewhb = (const float*)d_in[9];
    const float* ebib = (const float*)d_in[10];
    const float* ebhb = (const float*)d_in[11];
    const float* projw = (const float*)d_in[12];
    const float* projb = (const float*)d_in[13];
    const float* dw1 = (const float*)d_in[14];
    const float* db1 = (const float*)d_in[15];
    const float* dw2 = (const float*)d_in[16];
    const float* db2 = (const float*)d_in[17];
    const float* dw3 = (const float*)d_in[18];
    const float* db3 = (const float*)d_in[19];
    const float* miw = (const float*)d_in[20];
    const float* mib = (const float*)d_in[21];
    const float* aiw = (const float*)d_in[22];
    const float* aib = (const float*)d_in[23];
    const float* aow = (const float*)d_in[24];
    const float* aob = (const float*)d_in[25];
    const float* dwih = (const float*)d_in[26];
    const float* dwhh = (const float*)d_in[27];
    const float* dbih = (const float*)d_in[28];
    const float* dbhh = (const float*)d_in[29];
    const float* mow = (const float*)d_in[30];
    const float* mob = (const float*)d_in[31];
    float* out = (float*)d_out;

    float* A;
    cudaGetSymbolAddress((void**)&A, g_arena);

    reset_bars_kernel<<<3, 256>>>();
    gather_emb_kernel<<<2048, 128>>>(ph, emb);
    // encoder input-gate precompute (includes b_ih)
    run_sgemm(A + OFF_X, 512, ewif, ebif, A + OFF_XGF, 2048, 2048, 2048, 512);
    run_sgemm(A + OFF_X, 512, ewib, ebib, A + OFF_XGB, 2048, 2048, 2048, 512);
    enc_lstm_kernel<<<128, 256>>>(ewhf, ewhb, ebhf, ebhb);
    run_sgemm(A + OFF_HFB, 1024, projw, projb, A + OFF_ENC, 512, 2048, 512, 1024);
    // duration predictor
    run_sgemm(A + OFF_ENC, 512, dw1, db1, A + OFF_H1, 512, 2048, 512, 512, true);
    run_sgemm(A + OFF_H1, 512, dw2, db2, A + OFF_H2, 256, 2048, 256, 512, true);
    logdur_kernel<<<8, 256>>>(dw3, db3, out + (size_t)8 * 1024 * 80);
    // attention path
    counts_kernel<<<8, 256>>>(dur);
    shift_mel_kernel<<<2560, 256>>>(mel);
    run_sgemm(A + OFF_MELIN, 80, miw, mib, A + OFF_DECIN, 1024, 8192, 512, 80); // q_in
    run_sgemm(A + OFF_DECIN, 1024, aiw, aib, A + OFF_Q, 512, 8192, 512, 512);  // Q
    run_sgemm(A + OFF_ENC, 512, aiw + (size_t)512 * 512, aib + 512,
              A + OFF_K, 512, 2048, 512, 512);                                  // K
    run_sgemm(A + OFF_ENC, 512, aiw + (size_t)1024 * 512, aib + 1024,
              A + OFF_V, 512, 2048, 512, 512);                                  // V
    cudaFuncSetAttribute(attn_kernel, cudaFuncAttributeMaxDynamicSharedMemorySize,
                         2 * 256 * 64 * (int)sizeof(float));
    attn_kernel<<<256, 256, 2 * 256 * 64 * sizeof(float)>>>();
    run_sgemm(A + OFF_CTX, 512, aow, aob, A + OFF_DECIN + 512, 1024,
              8192, 512, 512);                                                  // attended
    // decoder
    run_sgemm(A + OFF_DECIN, 1024, dwih, dbih, A + OFF_DXG, 2048,
              8192, 2048, 1024);
    dec_lstm_kernel<<<128, 256>>>(dwhh, dbhh);
    run_sgemm(A + OFF_DOUT, 512, mow, mob, out, 80, 8192, 80, 512);             // mel_pred
}

// round 17
// speedup vs baseline: 1.4041x; 1.2537x over previous
#include <cuda_runtime.h>
#include <cuda_bf16.h>
#include <math.h>

// dims: B=8, T_TEXT=256, T_MEL=1024, VOCAB=256, MEL=80, H=512, NH=8, HD=64

// ------------------------- scratch arena -----------------------------------
constexpr size_t OFF_X     = 0;                               // [2048,512]
constexpr size_t OFF_XGF   = OFF_X     + (size_t)2048*512;    // [2048,2048]
constexpr size_t OFF_XGB   = OFF_XGF   + (size_t)2048*2048;   // [2048,2048]
constexpr size_t OFF_HFB   = OFF_XGB   + (size_t)2048*2048;   // [2048,1024]
constexpr size_t OFF_ENC   = OFF_HFB   + (size_t)2048*1024;   // [2048,512]
constexpr size_t OFF_H1    = OFF_ENC   + (size_t)2048*512;    // [2048,512]
constexpr size_t OFF_H2    = OFF_H1    + (size_t)2048*512;    // [2048,256]
constexpr size_t OFF_CNT   = OFF_H2    + (size_t)2048*256;    // [8,256]
constexpr size_t OFF_MELIN = OFF_CNT   + (size_t)8*256;       // [8192,80]
constexpr size_t OFF_K     = OFF_MELIN + (size_t)8192*80;     // [2048,512]
constexpr size_t OFF_V     = OFF_K     + (size_t)2048*512;    // [2048,512]
constexpr size_t OFF_DECIN = OFF_V     + (size_t)2048*512;    // [8192,1024]
constexpr size_t OFF_Q     = OFF_DECIN + (size_t)8192*1024;   // [8192,512]
constexpr size_t OFF_CTX   = OFF_Q     + (size_t)8192*512;    // [8192,512]
constexpr size_t OFF_DXG   = OFF_CTX   + (size_t)8192*512;    // [8192,2048]
constexpr size_t OFF_DOUT  = OFF_DXG   + (size_t)8192*2048;   // [8192,512]
constexpr size_t OFF_HBUF  = OFF_DOUT  + (size_t)8192*512;    // 8*4096 (4 groups x 2 bufs)
constexpr size_t ARENA_SZ  = OFF_HBUF  + (size_t)8*4096;

__device__ __align__(16) float g_arena[ARENA_SZ];
// one counter per barrier group (enc fwd, enc bwd, dec lo, dec hi), own lines
__device__ unsigned g_cntarr[4 * 32];

__global__ void reset_bars_kernel() {
    if (threadIdx.x < 4 * 32) g_cntarr[threadIdx.x] = 0u;
}

__global__ void gather_emb_kernel(const int* __restrict__ idx, const float* __restrict__ emb) {
    int bt = blockIdx.x;
    const float4* s = reinterpret_cast<const float4*>(emb + (size_t)idx[bt] * 512);
    float4* d = reinterpret_cast<float4*>(g_arena + OFF_X + (size_t)bt * 512);
    d[threadIdx.x] = __ldg(s + threadIdx.x);
}

__global__ void shift_mel_kernel(const float* __restrict__ mel) {
    int i = blockIdx.x * 256 + threadIdx.x;
    if (i < 8 * 1024 * 80) {
        int t = (i % (1024 * 80)) / 80;
        g_arena[OFF_MELIN + i] = (t == 0) ? 0.f : mel[i - 80];
    }
}

__global__ void counts_kernel(const float* __restrict__ dur) {
    __shared__ int cum[256];
    int b = blockIdx.x, t = threadIdx.x;
    cum[t] = (int)rintf(dur[b * 256 + t]);
    __syncthreads();
    for (int off = 1; off < 256; off <<= 1) {
        int add = (t >= off) ? cum[t - off] : 0;
        __syncthreads();
        cum[t] += add;
        __syncthreads();
    }
    int hi = min(cum[t], 1024);
    int lo = (t > 0) ? min(cum[t - 1], 1024) : 0;
    g_arena[OFF_CNT + b * 256 + t] = (float)(hi - lo);
}

// ---------------- fp32 SGEMM: C[M,N] = A[M,K] @ W[N,K]^T + bias ------------
// 128x128 tile, K-slice 8, double-buffered smem + per-kk fragment pipeline.
template <bool RELU>
__global__ void __launch_bounds__(256) sgemm_kernel(
    const float* __restrict__ A, int lda, const float* __restrict__ W,
    const float* __restrict__ bias, float* __restrict__ C, int ldc,
    int M, int N, int K)
{
    __shared__ float As[2][8][128];
    __shared__ float Bs[2][8][128];
    const int tid = threadIdx.x;
    const int lrow = tid >> 1, lkq = (tid & 1) << 2;
    const int tx = tid & 15, ty = tid >> 4;
    const int mBase = blockIdx.y * 128, nBase = blockIdx.x * 128;
    float acc[8][8];
#pragma unroll
    for (int i = 0; i < 8; i++)
#pragma unroll
        for (int j = 0; j < 8; j++) acc[i][j] = 0.f;
    const int am = mBase + lrow, bn = nBase + lrow;
    const float* aptr = A + (size_t)am * lda + lkq;
    const float* wptr = W + (size_t)bn * K + lkq;

    float4 av = make_float4(0.f, 0.f, 0.f, 0.f), bv = av;
    if (am < M) av = *reinterpret_cast<const float4*>(aptr);
    if (bn < N) bv = *reinterpret_cast<const float4*>(wptr);
    As[0][lkq + 0][lrow] = av.x; As[0][lkq + 1][lrow] = av.y;
    As[0][lkq + 2][lrow] = av.z; As[0][lkq + 3][lrow] = av.w;
    Bs[0][lkq + 0][lrow] = bv.x; Bs[0][lkq + 1][lrow] = bv.y;
    Bs[0][lkq + 2][lrow] = bv.z; Bs[0][lkq + 3][lrow] = bv.w;
    __syncthreads();

    int p = 0;
    for (int k0 = 0; k0 < K; k0 += 8) {
        bool more = (k0 + 8) < K;
        if (more) {
            av = make_float4(0.f, 0.f, 0.f, 0.f); bv = av;
            if (am < M) av = *reinterpret_cast<const float4*>(aptr + k0 + 8);
            if (bn < N) bv = *reinterpret_cast<const float4*>(wptr + k0 + 8);
        }
        float4 a0 = *reinterpret_cast<const float4*>(&As[p][0][ty * 8]);
        float4 a1 = *reinterpret_cast<const float4*>(&As[p][0][ty * 8 + 4]);
        float4 b0 = *reinterpret_cast<const float4*>(&Bs[p][0][tx * 8]);
        float4 b1 = *reinterpret_cast<const float4*>(&Bs[p][0][tx * 8 + 4]);
#pragma unroll
        for (int kk = 0; kk < 8; kk++) {
            float4 na0, na1, nb0, nb1;
            if (kk < 7) {
                na0 = *reinterpret_cast<const float4*>(&As[p][kk + 1][ty * 8]);
                na1 = *reinterpret_cast<const float4*>(&As[p][kk + 1][ty * 8 + 4]);
                nb0 = *reinterpret_cast<const float4*>(&Bs[p][kk + 1][tx * 8]);
                nb1 = *reinterpret_cast<const float4*>(&Bs[p][kk + 1][tx * 8 + 4]);
            }
            float ar[8] = {a0.x, a0.y, a0.z, a0.w, a1.x, a1.y, a1.z, a1.w};
            float br[8] = {b0.x, b0.y, b0.z, b0.w, b1.x, b1.y, b1.z, b1.w};
#pragma unroll
            for (int i = 0; i < 8; i++)
#pragma unroll
                for (int j = 0; j < 8; j++) acc[i][j] = fmaf(ar[i], br[j], acc[i][j]);
            if (kk < 7) { a0 = na0; a1 = na1; b0 = nb0; b1 = nb1; }
        }
        if (more) {
            int q = p ^ 1;
            As[q][lkq + 0][lrow] = av.x; As[q][lkq + 1][lrow] = av.y;
            As[q][lkq + 2][lrow] = av.z; As[q][lkq + 3][lrow] = av.w;
            Bs[q][lkq + 0][lrow] = bv.x; Bs[q][lkq + 1][lrow] = bv.y;
            Bs[q][lkq + 2][lrow] = bv.z; Bs[q][lkq + 3][lrow] = bv.w;
            __syncthreads();
            p = q;
        }
    }
#pragma unroll
    for (int i = 0; i < 8; i++) {
        int m = mBase + ty * 8 + i;
        if (m >= M) continue;
#pragma unroll
        for (int j = 0; j < 8; j++) {
            int n = nBase + tx * 8 + j;
            if (n >= N) continue;
            float v = acc[i][j] + bias[n];
            if (RELU) v = fmaxf(v, 0.f);
            C[(size_t)m * ldc + n] = v;
        }
    }
}

// ---------------- persistent LSTM recurrence -------------------------------
__device__ __forceinline__ float sigf(float x) { return 1.0f / (1.0f + expf(-x)); }

__device__ __forceinline__ unsigned ld_acq(const unsigned* p) {
    unsigned v;
    asm volatile("ld.acquire.gpu.global.u32 %0, [%1];" : "=r"(v) : "l"(p) : "memory");
    return v;
}
__device__ __forceinline__ void red_rel_add1(unsigned* p) {
    asm volatile("red.release.gpu.global.add.u32 [%0], 1;" :: "l"(p) : "memory");
}
// arrive: all prior CTA writes happen-before (bar.sync) the release RED
__device__ __forceinline__ void bar_arrive(unsigned* cnt) {
    __syncthreads();
    if (threadIdx.x == 0) red_rel_add1(cnt);
}
// wait: thread 0 acquire-polls the group counter (R10 scheme, measured best)
__device__ __forceinline__ void bar_wait(unsigned* cnt, unsigned target) {
    if (threadIdx.x == 0) {
        while (ld_acq(cnt) < target) { }
    }
    __syncthreads();
}

// JPC hidden units per CTA, KCN k-chunks (4*JPC*KCN == 256 threads),
// NB batches owned by this barrier group, bOff = first batch index.
template <int JPC, int KCN, int NB>
__device__ __forceinline__ void lstm_core(
    const float* __restrict__ xg, const float* __restrict__ W,
    const float* __restrict__ bhh, float* __restrict__ out,
    int outStride, int outOffset, float* hbuf, int bOff,
    unsigned* cnt, int T, bool reverse, int rcta, unsigned nCTA)
{
    constexpr int GPC = 4 * JPC;
    constexpr int CHUNK = 512 / KCN;
    constexpr int NBH = NB * 512;        // floats per h buffer
    const int tid = threadIdx.x;
    const int g_local = tid % GPC, kc = tid / GPC;
    const int type = g_local & 3, j_loc = g_local >> 2;
    const int gate_g = type * 512 + rcta * JPC + j_loc;

    float w[CHUNK];
    {
        const float4* wp = reinterpret_cast<const float4*>(W + (size_t)gate_g * 512 + kc * CHUNK);
#pragma unroll
        for (int i = 0; i < CHUNK / 4; i++) {
            float4 t4 = __ldg(wp + i);
            w[4*i] = t4.x; w[4*i+1] = t4.y; w[4*i+2] = t4.z; w[4*i+3] = t4.w;
        }
    }

    // reduce-phase mapping: threads tid < GPC*NB
    const int red_g = tid / NB, red_b = tid % NB;
    const int red_gg = (red_g & 3) * 512 + rcta * JPC + (red_g >> 2);
    const float bconst = (tid < GPC * NB) ? __ldg(bhh + red_gg) : 0.f;

    __shared__ float h_sm[NBH];
    __shared__ float partial[256 * NB];
    __shared__ float gsm[GPC * NB];
    __shared__ float c_sm[JPC * NB];

    if (tid < JPC * NB) {
        c_sm[tid] = 0.f;
        int jl = tid / NB, b = tid % NB;
        __stcg(hbuf + b * 512 + rcta * JPC + jl, 0.f);
    }
    bar_arrive(cnt);

    unsigned epoch = nCTA;
    for (int s = 0; s < T; s++) {
        const int t = reverse ? (T - 1 - s) : s;
        // prefetch this step's xg gate value BEFORE the barrier wait
        float xval = 0.f;
        if (tid < GPC * NB)
            xval = __ldg(xg + ((size_t)(red_b + bOff) * T + t) * 2048 + red_gg) + bconst;

        bar_wait(cnt, epoch);
        {
            const float4* hb4 = reinterpret_cast<const float4*>(hbuf + (s & 1) * NBH);
            float4* hs4 = reinterpret_cast<float4*>(h_sm);
            for (int i = tid; i < NBH / 4; i += 256) hs4[i] = __ldcg(hb4 + i);
        }
        __syncthreads();
#pragma unroll
        for (int b = 0; b < NB; b++) {
            const float* hp = h_sm + b * 512 + kc * CHUNK;
            float a = 0.f;
#pragma unroll
            for (int i = 0; i < CHUNK; i += 4) {
                float4 h4 = *reinterpret_cast<const float4*>(hp + i);
                a = fmaf(h4.x, w[i], a);   a = fmaf(h4.y, w[i+1], a);
                a = fmaf(h4.z, w[i+2], a); a = fmaf(h4.w, w[i+3], a);
            }
            partial[(kc * GPC + g_local) * NB + b] = a;
        }
        __syncthreads();
        if (tid < GPC * NB) {
            float acc = xval;
#pragma unroll
            for (int q = 0; q < KCN; q++) acc += partial[(q * GPC + red_g) * NB + red_b];
            gsm[red_g * NB + red_b] = acc;
        }
        __syncthreads();
        if (tid < JPC * NB) {
            int jl = tid / NB, b = tid % NB;
            float gi = gsm[(jl * 4 + 0) * NB + b];
            float gf = gsm[(jl * 4 + 1) * NB + b];
            float gc = gsm[(jl * 4 + 2) * NB + b];
            float go = gsm[(jl * 4 + 3) * NB + b];
            float c = sigf(gf) * c_sm[tid] + sigf(gi) * tanhf(gc);
            float hv = sigf(go) * tanhf(c);
            c_sm[tid] = c;
            int j2 = rcta * JPC + jl;
            __stcg(hbuf + ((s + 1) & 1) * NBH + b * 512 + j2, hv);
            out[((size_t)(b + bOff) * T + t) * outStride + outOffset + j2] = hv;
        }
        bar_arrive(cnt);
        epoch += nCTA;
    }
}

// encoder: 2 groups x 64 CTAs, 8 batches each (as in R10, measured best)
__global__ void __launch_bounds__(256) enc_lstm_kernel(
    const float* __restrict__ Wf, const float* __restrict__ Wb,
    const float* __restrict__ bf, const float* __restrict__ bb)
{
    int group = blockIdx.x >> 6, rcta = blockIdx.x & 63;
    float* hfb = g_arena + OFF_HFB;
    float* hbuf = g_arena + OFF_HBUF + (size_t)group * 2 * 4096;
    unsigned* cnt = g_cntarr + group * 32;
    if (group == 0)
        lstm_core<8, 8, 8>(g_arena + OFF_XGF, Wf, bf, hfb, 1024, 0, hbuf, 0,
                           cnt, 256, false, rcta, 64u);
    else
        lstm_core<8, 8, 8>(g_arena + OFF_XGB, Wb, bb, hfb, 1024, 512, hbuf, 0,
                           cnt, 256, true, rcta, 64u);
}

// decoder: 2 INDEPENDENT groups x 64 CTAs, 4 batches each — decoupled
// barriers (halved straggler pool, halved fan-in, same per-thread FMA)
__global__ void __launch_bounds__(256) dec_lstm_kernel(
    const float* __restrict__ Whh, const float* __restrict__ bhh)
{
    int group = blockIdx.x >> 6, rcta = blockIdx.x & 63;
    float* hbuf = g_arena + OFF_HBUF + (size_t)(2 + group) * 2 * 4096;
    unsigned* cnt = g_cntarr + (2 + group) * 32;
    lstm_core<8, 8, 4>(g_arena + OFF_DXG, Whh, bhh, g_arena + OFF_DOUT, 512, 0,
                       hbuf, group * 4, cnt, 1024, false, rcta, 64u);
}

// ---------------- multiplicity-compressed attention ------------------------
extern __shared__ float sm_attn[];
__global__ void __launch_bounds__(256) attn_kernel()
{
    float* ksm = sm_attn;
    float* vsm = sm_attn + 256 * 64;
    __shared__ float csm[256];
    const int tid = threadIdx.x, bid = blockIdx.x;
    const int qc = bid & 3, h = (bid >> 2) & 7, b = bid >> 5;
    {
        const float4* ks = reinterpret_cast<const float4*>(
            g_arena + OFF_K + ((size_t)b * 256 + tid) * 512 + h * 64);
        const float4* vs = reinterpret_cast<const float4*>(
            g_arena + OFF_V + ((size_t)b * 256 + tid) * 512 + h * 64);
        float4* kd = reinterpret_cast<float4*>(ksm + tid * 64);
        float4* vd = reinterpret_cast<float4*>(vsm + tid * 64);
#pragma unroll
        for (int i = 0; i < 16; i++) { kd[i] = __ldg(ks + i); vd[i] = __ldg(vs + i); }
        csm[tid] = g_arena[OFF_CNT + b * 256 + tid];
    }
    __syncthreads();
    const int qi = qc * 256 + tid;
    float qr[64], acc[64];
    {
        const float4* qs = reinterpret_cast<const float4*>(
            g_arena + OFF_Q + ((size_t)b * 1024 + qi) * 512 + h * 64);
#pragma unroll
        for (int i = 0; i < 16; i++) {
            float4 t4 = __ldg(qs + i);
            qr[4*i] = t4.x; qr[4*i+1] = t4.y; qr[4*i+2] = t4.z; qr[4*i+3] = t4.w;
        }
    }
#pragma unroll
    for (int d = 0; d < 64; d++) acc[d] = 0.f;
    float m = -1e30f, l = 0.f;
    for (int j = 0; j < 256; j++) {
        float c = csm[j];
        if (c == 0.f) continue;   // exact: pad keys get weight expf(-1e9-m)==0
        const float4* kr = reinterpret_cast<const float4*>(ksm + j * 64);
        float s = 0.f;
#pragma unroll
        for (int i = 0; i < 16; i++) {
            float4 k4 = kr[i];
            s = fmaf(qr[4*i], k4.x, s);   s = fmaf(qr[4*i+1], k4.y, s);
            s = fmaf(qr[4*i+2], k4.z, s); s = fmaf(qr[4*i+3], k4.w, s);
        }
        s *= 0.125f;
        float wgt;
        if (s > m) {
            float corr = __expf(m - s);
            l *= corr;
#pragma unroll
            for (int d = 0; d < 64; d++) acc[d] *= corr;
            m = s; wgt = c;
        } else {
            wgt = c * __expf(s - m);
        }
        l += wgt;
        const float4* vr = reinterpret_cast<const float4*>(vsm + j * 64);
#pragma unroll
        for (int i = 0; i < 16; i++) {
            float4 v4 = vr[i];
            acc[4*i]   = fmaf(wgt, v4.x, acc[4*i]);
            acc[4*i+1] = fmaf(wgt, v4.y, acc[4*i+1]);
            acc[4*i+2] = fmaf(wgt, v4.z, acc[4*i+2]);
            acc[4*i+3] = fmaf(wgt, v4.w, acc[4*i+3]);
        }
    }
    float inv = 1.0f / l;
    float4* cd = reinterpret_cast<float4*>(
        g_arena + OFF_CTX + ((size_t)b * 1024 + qi) * 512 + h * 64);
#pragma unroll
    for (int i = 0; i < 16; i++)
        cd[i] = make_float4(acc[4*i] * inv, acc[4*i+1] * inv,
                            acc[4*i+2] * inv, acc[4*i+3] * inv);
}

__global__ void logdur_kernel(const float* __restrict__ w3,
                              const float* __restrict__ b3, float* __restrict__ out) {
    int i = blockIdx.x * 256 + threadIdx.x;   // 2048 rows
    const float* h2 = g_arena + OFF_H2 + (size_t)i * 256;
    float s = b3[0];
    for (int k = 0; k < 256; k += 4) {
        float4 a = *reinterpret_cast<const float4*>(h2 + k);
        float4 w = __ldg(reinterpret_cast<const float4*>(w3 + k));
        s = fmaf(a.x, w.x, s); s = fmaf(a.y, w.y, s);
        s = fmaf(a.z, w.z, s); s = fmaf(a.w, w.w, s);
    }
    out[i] = s;
}

// ---------------------------------------------------------------------------
static inline void run_sgemm(const float* A, int lda, const float* W,
                             const float* bias, float* C, int ldc,
                             int M, int N, int K, bool relu = false) {
    dim3 grid((N + 127) / 128, (M + 127) / 128);
    if (relu) sgemm_kernel<true><<<grid, 256>>>(A, lda, W, bias, C, ldc, M, N, K);
    else      sgemm_kernel<false><<<grid, 256>>>(A, lda, W, bias, C, ldc, M, N, K);
}

extern "C" void kernel_launch(void* const* d_in, const int* in_sizes, int n_in,
                              void* d_out, int out_size) {
    const int*   ph   = (const int*)  d_in[0];
    const float* mel  = (const float*)d_in[1];
    const float* dur  = (const float*)d_in[2];
    const float* emb  = (const float*)d_in[3];
    const float* ewif = (const float*)d_in[4];
    const float* ewhf = (const float*)d_in[5];
    const float* ebif = (const float*)d_in[6];
    const float* ebhf = (const float*)d_in[7];
    const float* ewib = (const float*)d_in[8];
    const float* ewhb = (const float*)d_in[9];
    const float* ebib = (const float*)d_in[10];
    const float* ebhb = (const float*)d_in[11];
    const float* projw = (const float*)d_in[12];
    const float* projb = (const float*)d_in[13];
    const float* dw1 = (const float*)d_in[14];
    const float* db1 = (const float*)d_in[15];
    const float* dw2 = (const float*)d_in[16];
    const float* db2 = (const float*)d_in[17];
    const float* dw3 = (const float*)d_in[18];
    const float* db3 = (const float*)d_in[19];
    const float* miw = (const float*)d_in[20];
    const float* mib = (const float*)d_in[21];
    const float* aiw = (const float*)d_in[22];
    const float* aib = (const float*)d_in[23];
    const float* aow = (const float*)d_in[24];
    const float* aob = (const float*)d_in[25];
    const float* dwih = (const float*)d_in[26];
    const float* dwhh = (const float*)d_in[27];
    const float* dbih = (const float*)d_in[28];
    const float* dbhh = (const float*)d_in[29];
    const float* mow = (const float*)d_in[30];
    const float* mob = (const float*)d_in[31];
    float* out = (float*)d_out;

    float* A;
    cudaGetSymbolAddress((void**)&A, g_arena);

    reset_bars_kernel<<<1, 128>>>();
    gather_emb_kernel<<<2048, 128>>>(ph, emb);
    // encoder input-gate precompute (includes b_ih)
    run_sgemm(A + OFF_X, 512, ewif, ebif, A + OFF_XGF, 2048, 2048, 2048, 512);
    run_sgemm(A + OFF_X, 512, ewib, ebib, A + OFF_XGB, 2048, 2048, 2048, 512);
    enc_lstm_kernel<<<128, 256>>>(ewhf, ewhb, ebhf, ebhb);
    run_sgemm(A + OFF_HFB, 1024, projw, projb, A + OFF_ENC, 512, 2048, 512, 1024);
    // duration predictor
    run_sgemm(A + OFF_ENC, 512, dw1, db1, A + OFF_H1, 512, 2048, 512, 512, true);
    run_sgemm(A + OFF_H1, 512, dw2, db2, A + OFF_H2, 256, 2048, 256, 512, true);
    logdur_kernel<<<8, 256>>>(dw3, db3, out + (size_t)8 * 1024 * 80);
    // attention path
    counts_kernel<<<8, 256>>>(dur);
    shift_mel_kernel<<<2560, 256>>>(mel);
    run_sgemm(A + OFF_MELIN, 80, miw, mib, A + OFF_DECIN, 1024, 8192, 512, 80); // q_in
    run_sgemm(A + OFF_DECIN, 1024, aiw, aib, A + OFF_Q, 512, 8192, 512, 512);  // Q
    run_sgemm(A + OFF_ENC, 512, aiw + (size_t)512 * 512, aib + 512,
              A + OFF_K, 512, 2048, 512, 512);                                  // K
    run_sgemm(A + OFF_ENC, 512, aiw + (size_t)1024 * 512, aib + 1024,
              A + OFF_V, 512, 2048, 512, 512);                                  // V
    cudaFuncSetAttribute(attn_kernel, cudaFuncAttributeMaxDynamicSharedMemorySize,
                         2 * 256 * 64 * (int)sizeof(float));
    attn_kernel<<<256, 256, 2 * 256 * 64 * sizeof(float)>>>();
    run_sgemm(A + OFF_CTX, 512, aow, aob, A + OFF_DECIN + 512, 1024,
              8192, 512, 512);                                                  // attended
    // decoder
    run_sgemm(A + OFF_DECIN, 1024, dwih, dbih, A + OFF_DXG, 2048,
              8192, 2048, 1024);
    dec_lstm_kernel<<<128, 256>>>(dwhh, dbhh);
    run_sgemm(A + OFF_DOUT, 512, mow, mob, out, 80, 8192, 80, 512);             // mel_pred
}